// round 4
// baseline (speedup 1.0000x reference)
#include <cuda_runtime.h>
#include <cstdint>

// Problem constants
#define T_C 4
#define N_C 20000
#define E_C 320000
#define FIN 12
#define EH 32
#define NH 64
#define GH 64

// ---------------- device scratch ----------------
__device__ float d_xenc[T_C * N_C * NH];
__device__ float d_xsA [T_C * N_C * NH];
__device__ float d_xsB [T_C * N_C * NH];
__device__ float d_es0 [(size_t)T_C * E_C * EH];
__device__ float d_e1  [(size_t)E_C * EH];
__device__ float d_hx0 [N_C * NH];
__device__ float d_ns  [N_C * NH];
__device__ float d_acc [N_C * NH];
__device__ float d_g[GH], d_gsave[GH];
__device__ float d_gce[EH];
__device__ float d_gcn[NH];
__device__ float d_esum[EH], d_xsum[NH];
__device__ float d_Pp[EH], d_Pm[EH];
__device__ int   d_fast0;

__device__ __forceinline__ float dot4(float4 v, float4 w) {
    return v.x * w.x + v.y * w.y + v.z * w.z + v.w * w.w;
}

// ---------------- small kernels ----------------

__global__ __launch_bounds__(256) void k_encode(const float* __restrict__ na,
                                                const float* __restrict__ W_ne,
                                                const float* __restrict__ b_ne,
                                                float* __restrict__ xenc) {
    __shared__ float sW[FIN * NH + NH];
    for (int i = threadIdx.x; i < FIN * NH + NH; i += 256)
        sW[i] = (i < FIN * NH) ? W_ne[i] : b_ne[i - FIN * NH];
    __syncthreads();
    int idx = blockIdx.x * 256 + threadIdx.x;
    int row = idx >> 6, j = idx & 63;
    float v = sW[FIN * NH + j];
#pragma unroll
    for (int k = 0; k < FIN; k++) v += na[row * FIN + k] * sW[k * NH + j];
    xenc[idx] = fmaxf(v, 0.f);
}

__global__ void k_prep(const float* __restrict__ W_ee, const float* __restrict__ b_ee,
                       const float* __restrict__ W_eb) {
    int j = threadIdx.x;  // 32
    float pp = 0.f, pm = 0.f;
    bool ok = true;
#pragma unroll
    for (int k = 0; k < EH; k++) {
        float w = W_ee[k];
        pp += fmaxf(w, 0.f)  * W_eb[k * EH + j];
        pm += fmaxf(-w, 0.f) * W_eb[k * EH + j];
        if (b_ee[k] != 0.f) ok = false;
    }
    d_Pp[j] = pp; d_Pm[j] = pm;
    if (j == 0) d_fast0 = ok ? 1 : 0;
}

__global__ void k_ginit(const float* __restrict__ g0,
                        const float* __restrict__ W_eb, const float* __restrict__ b_eb,
                        const float* __restrict__ W_nb, const float* __restrict__ b_nb) {
    __shared__ float g[GH];
    int tid = threadIdx.x;  // 96
    if (tid < GH) { g[tid] = g0[tid]; d_g[tid] = g0[tid]; }
    __syncthreads();
    if (tid < EH) {
        float v = b_eb[tid];
#pragma unroll
        for (int k = 0; k < GH; k++) v += g[k] * W_eb[(320 + k) * EH + tid];
        d_gce[tid] = v;
    } else if (tid < 32 + NH) {
        int j = tid - 32;
        float v = b_nb[j];
#pragma unroll
        for (int k = 0; k < GH; k++) v += g[k] * W_nb[(192 + k) * NH + j];
        d_gcn[j] = v;
    }
}

__global__ void k_global(const float* __restrict__ W_gb, const float* __restrict__ b_gb,
                         const float* __restrict__ W_eb, const float* __restrict__ b_eb,
                         const float* __restrict__ W_nb, const float* __restrict__ b_nb,
                         int save) {
    __shared__ float gcat[160], gnew[GH];
    int tid = threadIdx.x;  // 256
    if (tid < 64) gcat[tid] = d_xsum[tid] * (1.0f / N_C);
    else if (tid < 96) gcat[tid] = d_esum[tid - 64] * (1.0f / E_C);
    else if (tid < 160) gcat[tid] = d_g[tid - 96];
    __syncthreads();
    if (tid < GH) {
        float v = b_gb[tid];
        for (int k = 0; k < 160; k++) v += gcat[k] * W_gb[k * GH + tid];
        gnew[tid] = fmaxf(v, 0.f);
    }
    __syncthreads();
    if (tid < GH) {
        d_g[tid] = gnew[tid];
        if (save) d_gsave[tid] = gnew[tid];
        d_xsum[tid] = 0.f;
    }
    if (tid < EH) d_esum[tid] = 0.f;
    if (tid < EH) {
        float v = b_eb[tid];
#pragma unroll
        for (int k = 0; k < GH; k++) v += gnew[k] * W_eb[(320 + k) * EH + tid];
        d_gce[tid] = v;
    } else if (tid < 32 + NH) {
        int j = tid - 32;
        float v = b_nb[j];
#pragma unroll
        for (int k = 0; k < GH; k++) v += gnew[k] * W_nb[(192 + k) * NH + j];
        d_gcn[j] = v;
    }
}

// ---------------- k_nodepre4: 32 nodes/block, 4 nodes/warp, grid 625 ----------------
__global__ __launch_bounds__(256) void k_nodepre4(const float* __restrict__ xin,
                                                  const float* __restrict__ hx,
                                                  const float* __restrict__ W_eb,
                                                  float* __restrict__ ns,
                                                  float* __restrict__ accbuf) {
    __shared__ float4 sW[64 * 33];   // out j (0..63) x 32 quads (16 x-part, 16 h-part)
    int tid = threadIdx.x;
    for (int idx = tid; idx < 64 * 32; idx += 256) {
        int j = idx >> 5, q = idx & 31;
        int row0 = ((q < 16) ? ((j < 32) ? 64 : 192) + 4 * q
                             : ((j < 32) ? 128 : 256) + 4 * (q - 16));
        int jj = j & 31;
        float4 w;
        w.x = W_eb[(row0 + 0) * EH + jj];
        w.y = W_eb[(row0 + 1) * EH + jj];
        w.z = W_eb[(row0 + 2) * EH + jj];
        w.w = W_eb[(row0 + 3) * EH + jj];
        sW[j * 33 + q] = w;
    }
    __syncthreads();
    int lane = tid & 31, wid = tid >> 5;
    int gn0 = blockIdx.x * 32 + wid * 4;     // N divisible by 32 -> no bounds checks
    const float4* px = (const float4*)(xin + (size_t)gn0 * 64);
    const float4* ph = (const float4*)(hx + (size_t)gn0 * 64);
    float aA[4], aB[4];
#pragma unroll
    for (int n = 0; n < 4; n++) { aA[n] = 0.f; aB[n] = 0.f; }
#pragma unroll
    for (int q = 0; q < 16; q++) {
        float4 wa = sW[lane * 33 + q], wb = sW[(lane + 32) * 33 + q];
#pragma unroll
        for (int n = 0; n < 4; n++) {
            float4 v = px[n * 16 + q];
            aA[n] += dot4(v, wa); aB[n] += dot4(v, wb);
        }
    }
#pragma unroll
    for (int q = 0; q < 16; q++) {
        float4 wa = sW[lane * 33 + 16 + q], wb = sW[(lane + 32) * 33 + 16 + q];
#pragma unroll
        for (int n = 0; n < 4; n++) {
            float4 v = ph[n * 16 + q];
            aA[n] += dot4(v, wa); aB[n] += dot4(v, wb);
        }
    }
    float* pns = ns + (size_t)gn0 * 64;
    float* pac = accbuf + (size_t)gn0 * 64;
#pragma unroll
    for (int n = 0; n < 4; n++) {
        pns[n * 64 + lane] = aA[n];
        pns[n * 64 + 32 + lane] = aB[n];
        pac[n * 64 + lane] = 0.f;
        pac[n * 64 + 32 + lane] = 0.f;
    }
}

// ---------------- k_edge4: 64 edges/block, 8 edges/warp, grid 5000 ----------------
template <bool L0, bool HE>
__global__ __launch_bounds__(256) void k_edge4(const int* __restrict__ eidx,
                                               const float* __restrict__ ea_t,
                                               const float* __restrict__ ein,
                                               const float* __restrict__ he,
                                               float* __restrict__ eout,
                                               const float* __restrict__ ns,
                                               float* __restrict__ accbuf,
                                               const float* __restrict__ W_eb,
                                               const float* __restrict__ W_ee,
                                               const float* __restrict__ b_ee) {
    __shared__ float4 sWA[32 * 9];   // rows 0..31 (e_in), out j, pad 9 quads
    __shared__ float4 sWB[HE ? 32 * 9 : 1];
    __shared__ float4 sWee[8], sBee[8];
    __shared__ float sa[L0 ? 64 : 1];
    __shared__ float sred[8 * 32];
    int tid = threadIdx.x;
    int lane = tid & 31, wid = tid >> 5;
    int fast = L0 ? d_fast0 : 0;

    for (int idx = tid; idx < 32 * 8; idx += 256) {
        int j = idx >> 3, q = idx & 7;
        float4 w;
        w.x = W_eb[(4 * q + 0) * EH + j];
        w.y = W_eb[(4 * q + 1) * EH + j];
        w.z = W_eb[(4 * q + 2) * EH + j];
        w.w = W_eb[(4 * q + 3) * EH + j];
        sWA[j * 9 + q] = w;
        if (HE) {
            float4 w2;
            w2.x = W_eb[(32 + 4 * q + 0) * EH + j];
            w2.y = W_eb[(32 + 4 * q + 1) * EH + j];
            w2.z = W_eb[(32 + 4 * q + 2) * EH + j];
            w2.w = W_eb[(32 + 4 * q + 3) * EH + j];
            sWB[j * 9 + q] = w2;
        }
    }
    int e0b = blockIdx.x * 64;
    if (L0) {
        if (tid < 64) sa[tid] = ea_t[e0b + tid];
        if (tid < 8) {
            sWee[tid] = *(const float4*)&W_ee[tid * 4];
            sBee[tid] = *(const float4*)&b_ee[tid * 4];
        }
    }
    float gce = d_gce[lane];
    float pp = 0.f, pm = 0.f;
    if (L0) { pp = d_Pp[lane]; pm = d_Pm[lane]; }
    __syncthreads();

    int e0 = e0b + wid * 8;
    float acc[8];
#pragma unroll
    for (int i = 0; i < 8; i++) acc[i] = gce;

    if (L0) {
        if (fast) {
#pragma unroll
            for (int i = 0; i < 8; i++) {
                float a = sa[wid * 8 + i];
                acc[i] += (a >= 0.f) ? a * pp : -a * pm;
            }
        } else {
#pragma unroll
            for (int q = 0; q < 8; q++) {
                float4 w = sWA[lane * 9 + q];
                float4 we = sWee[q], be = sBee[q];
#pragma unroll
                for (int i = 0; i < 8; i++) {
                    float a = sa[wid * 8 + i];
                    float4 v;
                    v.x = fmaxf(a * we.x + be.x, 0.f);
                    v.y = fmaxf(a * we.y + be.y, 0.f);
                    v.z = fmaxf(a * we.z + be.z, 0.f);
                    v.w = fmaxf(a * we.w + be.w, 0.f);
                    acc[i] += dot4(v, w);
                }
            }
        }
    } else {
        const float4* pe = (const float4*)(ein + (size_t)e0 * 32);
#pragma unroll
        for (int q = 0; q < 8; q++) {
            float4 w = sWA[lane * 9 + q];
#pragma unroll
            for (int i = 0; i < 8; i++) {
                float4 v = pe[i * 8 + q];
                acc[i] += dot4(v, w);
            }
        }
    }
    if (HE) {
        const float4* pe = (const float4*)(he + (size_t)e0 * 32);
#pragma unroll
        for (int q = 0; q < 8; q++) {
            float4 w = sWB[lane * 9 + q];
#pragma unroll
            for (int i = 0; i < 8; i++) {
                float4 v = pe[i * 8 + q];
                acc[i] += dot4(v, w);
            }
        }
    }

    float esum = 0.f;
#pragma unroll 4
    for (int i = 0; i < 8; i++) {
        int e = e0 + i;
        int s = __ldg(&eidx[e]);
        int r = __ldg(&eidx[E_C + e]);
        float t1 = ns[(size_t)s * 64 + lane];
        float t2 = ns[(size_t)r * 64 + 32 + lane];
        float en = fmaxf(acc[i] + t1 + t2, 0.f);
        eout[(size_t)e * 32 + lane] = en;
        atomicAdd(&accbuf[(size_t)s * 64 + lane], en);
        atomicAdd(&accbuf[(size_t)r * 64 + 32 + lane], en);
        esum += en;
    }
    sred[wid * 32 + lane] = esum;
    __syncthreads();
    if (wid == 0) {
        float s2 = 0.f;
#pragma unroll
        for (int w = 0; w < 8; w++) s2 += sred[w * 32 + lane];
        atomicAdd(&d_esum[lane], s2);
    }
}

// ---------------- k_node4: 32 nodes/block, 4 nodes/warp, grid 625 ----------------
__global__ __launch_bounds__(256) void k_node4(const float* __restrict__ xin,
                                               const float* __restrict__ hx,
                                               const float* __restrict__ accbuf,
                                               const float* __restrict__ W_nb,
                                               float* __restrict__ xsout,
                                               float* __restrict__ tdout) {
    __shared__ float4 sW[64 * 49];   // out j (0..63) x 48 quads
    __shared__ float sred[8 * 64];
    int tid = threadIdx.x;
    for (int idx = tid; idx < 64 * 48; idx += 256) {
        int j = idx / 48;
        int q = idx - j * 48;
        float4 w;
        w.x = W_nb[(4 * q + 0) * NH + j];
        w.y = W_nb[(4 * q + 1) * NH + j];
        w.z = W_nb[(4 * q + 2) * NH + j];
        w.w = W_nb[(4 * q + 3) * NH + j];
        sW[j * 49 + q] = w;
    }
    __syncthreads();
    int lane = tid & 31, wid = tid >> 5;
    int gn0 = blockIdx.x * 32 + wid * 4;
    const float4* px = (const float4*)(xin + (size_t)gn0 * 64);
    const float4* ph = (const float4*)(hx + (size_t)gn0 * 64);
    const float4* pa = (const float4*)(accbuf + (size_t)gn0 * 64);
    float aA[4], aB[4];
#pragma unroll
    for (int n = 0; n < 4; n++) { aA[n] = 0.f; aB[n] = 0.f; }
#pragma unroll
    for (int q = 0; q < 16; q++) {
        float4 wa = sW[lane * 49 + q], wb = sW[(lane + 32) * 49 + q];
#pragma unroll
        for (int n = 0; n < 4; n++) {
            float4 v = px[n * 16 + q];
            aA[n] += dot4(v, wa); aB[n] += dot4(v, wb);
        }
    }
#pragma unroll
    for (int q = 0; q < 16; q++) {
        float4 wa = sW[lane * 49 + 16 + q], wb = sW[(lane + 32) * 49 + 16 + q];
#pragma unroll
        for (int n = 0; n < 4; n++) {
            float4 v = ph[n * 16 + q];
            aA[n] += dot4(v, wa); aB[n] += dot4(v, wb);
        }
    }
#pragma unroll
    for (int q = 0; q < 16; q++) {
        float4 wa = sW[lane * 49 + 32 + q], wb = sW[(lane + 32) * 49 + 32 + q];
#pragma unroll
        for (int n = 0; n < 4; n++) {
            float4 v = pa[n * 16 + q];
            aA[n] += dot4(v, wa); aB[n] += dot4(v, wb);
        }
    }
    float gA = d_gcn[lane], gB = d_gcn[32 + lane];
    float sA = 0.f, sB = 0.f;
    float* pxs = xsout + (size_t)gn0 * 64;
#pragma unroll
    for (int n = 0; n < 4; n++) {
        float lo = fmaxf(aA[n] + gA, 0.f);
        float hi = fmaxf(aB[n] + gB, 0.f);
        pxs[n * 64 + lane] = lo;
        pxs[n * 64 + 32 + lane] = hi;
        if (tdout) {
            const float* phf = (const float*)ph;
            tdout[(size_t)(gn0 + n) * 64 + lane]      = lo - phf[n * 64 + lane];
            tdout[(size_t)(gn0 + n) * 64 + 32 + lane] = hi - phf[n * 64 + 32 + lane];
        }
        sA += lo; sB += hi;
    }
    sred[wid * 64 + lane] = sA;
    sred[wid * 64 + 32 + lane] = sB;
    __syncthreads();
    if (tid < 64) {
        float s2 = 0.f;
#pragma unroll
        for (int w = 0; w < 8; w++) s2 += sred[w * 64 + tid];
        atomicAdd(&d_xsum[tid], s2);
    }
}

// ---------------- sder / resid / decode ----------------
__global__ __launch_bounds__(256) void k_sder(const int* __restrict__ eidx,
                                              const float* __restrict__ spL,
                                              const float* __restrict__ coeff,
                                              const float* __restrict__ xs,
                                              float* __restrict__ sd) {
    int tid = threadIdx.x, lane = tid & 31, wid = tid >> 5;
    int e = blockIdx.x * 8 + wid;
    int s = eidx[e], r = eidx[E_C + e];
    float cw = coeff[0] * spL[e];
    size_t bs = (size_t)s * NH, br = (size_t)r * NH;
    float d0 = cw * (xs[bs + lane] - xs[br + lane]);
    float d1 = cw * (xs[bs + 32 + lane] - xs[br + 32 + lane]);
    atomicAdd(&sd[br + lane], d0);
    atomicAdd(&sd[br + 32 + lane], d1);
}

__global__ __launch_bounds__(256) void k_resid(float* __restrict__ a, const float* __restrict__ b) {
    int i = blockIdx.x * 256 + threadIdx.x;
    a[i] += b[i];
}

__global__ __launch_bounds__(256) void k_decode(const float* __restrict__ xa,
                                                const float* __restrict__ xb,
                                                const float* __restrict__ W1,
                                                const float* __restrict__ b1,
                                                const float* __restrict__ W2,
                                                const float* __restrict__ b2,
                                                float* __restrict__ outn) {
    __shared__ float sw2[NH];
    __shared__ float4 sW1[64 * 17];
    int tid = threadIdx.x;
    for (int idx = tid; idx < 64 * 16; idx += 256) {
        int j = idx >> 4, q = idx & 15;
        float4 w;
        w.x = W1[(4 * q + 0) * NH + j];
        w.y = W1[(4 * q + 1) * NH + j];
        w.z = W1[(4 * q + 2) * NH + j];
        w.w = W1[(4 * q + 3) * NH + j];
        sW1[j * 17 + q] = w;
    }
    if (tid < NH) sw2[tid] = W2[tid];
    __syncthreads();
    int lane = tid & 31, wid = tid >> 5;
    int row0 = blockIdx.x * 32 + wid * 4;
    const float4* pa4 = (const float4*)(xa + (size_t)row0 * 64);
    const float4* pb4 = (const float4*)(xb + (size_t)row0 * 64);
    float aA[4], aB[4];
#pragma unroll
    for (int n = 0; n < 4; n++) { aA[n] = 0.f; aB[n] = 0.f; }
#pragma unroll
    for (int q = 0; q < 16; q++) {
        float4 wa = sW1[lane * 17 + q], wb = sW1[(lane + 32) * 17 + q];
#pragma unroll
        for (int n = 0; n < 4; n++) {
            float4 va = pa4[n * 16 + q];
            float4 vb = pb4[n * 16 + q];
            float4 v;
            v.x = va.x + vb.x; v.y = va.y + vb.y; v.z = va.z + vb.z; v.w = va.w + vb.w;
            aA[n] += dot4(v, wa); aB[n] += dot4(v, wb);
        }
    }
    float b1a = b1[lane], b1b = b1[32 + lane];
    float w2a = sw2[lane], w2b = sw2[32 + lane];
#pragma unroll
    for (int n = 0; n < 4; n++) {
        float lo = fmaxf(aA[n] + b1a, 0.f);
        float hi = fmaxf(aB[n] + b1b, 0.f);
        float p = lo * w2a + hi * w2b;
#pragma unroll
        for (int o = 16; o; o >>= 1) p += __shfl_down_sync(0xffffffffu, p, o);
        if (lane == 0) outn[row0 + n] = p + b2[0];
    }
}

// ---------------- host launcher ----------------
extern "C" void kernel_launch(void* const* d_in, const int* in_sizes, int n_in,
                              void* d_out, int out_size) {
    const float* node_attr  = (const float*)d_in[0];
    const float* edge_attr  = (const float*)d_in[1];
    const int*   edge_index = (const int*)  d_in[2];
    const float* spL        = (const float*)d_in[3];
    const float* gattr      = (const float*)d_in[4];
    const float* coeff      = (const float*)d_in[5];
    const float* W_ee = (const float*)d_in[6];
    const float* b_ee = (const float*)d_in[7];
    const float* W_ne = (const float*)d_in[8];
    const float* b_ne = (const float*)d_in[9];
    const float* W_eb = (const float*)d_in[10];
    const float* b_eb = (const float*)d_in[11];
    const float* W_nb = (const float*)d_in[12];
    const float* b_nb = (const float*)d_in[13];
    const float* W_gb = (const float*)d_in[14];
    const float* b_gb = (const float*)d_in[15];
    const float* W_nd1 = (const float*)d_in[16];
    const float* b_nd1 = (const float*)d_in[17];
    const float* W_nd2 = (const float*)d_in[18];
    const float* b_nd2 = (const float*)d_in[19];

    float* out    = (float*)d_out;
    float* out_td = out + (size_t)T_C * N_C;
    float* out_sd = out_td + (size_t)T_C * N_C * NH;

    float *xenc, *xsA, *xsB, *es0, *e1, *hx0, *ns, *acc, *gsave, *esum, *xsum;
    cudaGetSymbolAddress((void**)&xenc, d_xenc);
    cudaGetSymbolAddress((void**)&xsA,  d_xsA);
    cudaGetSymbolAddress((void**)&xsB,  d_xsB);
    cudaGetSymbolAddress((void**)&es0,  d_es0);
    cudaGetSymbolAddress((void**)&e1,   d_e1);
    cudaGetSymbolAddress((void**)&hx0,  d_hx0);
    cudaGetSymbolAddress((void**)&ns,   d_ns);
    cudaGetSymbolAddress((void**)&acc,  d_acc);
    cudaGetSymbolAddress((void**)&gsave, d_gsave);
    cudaGetSymbolAddress((void**)&esum, d_esum);
    cudaGetSymbolAddress((void**)&xsum, d_xsum);

    const int NGRID = N_C / 32;      // 625
    const int EGRID = E_C / 64;      // 5000

    cudaMemsetAsync(hx0, 0, (size_t)N_C * NH * sizeof(float));
    cudaMemsetAsync(esum, 0, EH * sizeof(float));
    cudaMemsetAsync(xsum, 0, NH * sizeof(float));
    cudaMemsetAsync(out_sd, 0, (size_t)T_C * N_C * NH * sizeof(float));

    k_encode<<<(T_C * N_C * NH) / 256, 256>>>(node_attr, W_ne, b_ne, xenc);
    k_prep<<<1, 32>>>(W_ee, b_ee, W_eb);

    // ---------------- layer 0 ----------------
    k_ginit<<<1, 96>>>(gattr, W_eb, b_eb, W_nb, b_nb);
    for (int t = 0; t < T_C; t++) {
        const float* xin = xenc + (size_t)t * N_C * NH;
        const float* hx = t ? (xsA + (size_t)(t - 1) * N_C * NH) : hx0;
        k_nodepre4<<<NGRID, 256>>>(xin, hx, W_eb, ns, acc);
        if (t == 0)
            k_edge4<true, false><<<EGRID, 256>>>(edge_index, edge_attr + (size_t)t * E_C,
                                                 nullptr, nullptr,
                                                 es0 + (size_t)t * E_C * EH, ns, acc,
                                                 W_eb, W_ee, b_ee);
        else
            k_edge4<true, true><<<EGRID, 256>>>(edge_index, edge_attr + (size_t)t * E_C,
                                                nullptr, es0 + (size_t)(t - 1) * E_C * EH,
                                                es0 + (size_t)t * E_C * EH, ns, acc,
                                                W_eb, W_ee, b_ee);
        k_node4<<<NGRID, 256>>>(xin, hx, acc, W_nb,
                                xsA + (size_t)t * N_C * NH, nullptr);
        if (t < T_C - 1)
            k_global<<<1, 256>>>(W_gb, b_gb, W_eb, b_eb, W_nb, b_nb, t == 0 ? 1 : 0);
    }

    k_resid<<<(T_C * N_C * NH) / 256, 256>>>(xsA, xenc);
    cudaMemsetAsync(esum, 0, EH * sizeof(float));
    cudaMemsetAsync(xsum, 0, NH * sizeof(float));

    // ---------------- layer 1 ----------------
    k_ginit<<<1, 96>>>(gsave, W_eb, b_eb, W_nb, b_nb);
    for (int t = 0; t < T_C; t++) {
        const float* xin = xsA + (size_t)t * N_C * NH;
        const float* hx = t ? (xsB + (size_t)(t - 1) * N_C * NH) : hx0;
        k_nodepre4<<<NGRID, 256>>>(xin, hx, W_eb, ns, acc);
        if (t == 0)
            k_edge4<false, false><<<EGRID, 256>>>(edge_index, nullptr,
                                                  es0 + (size_t)t * E_C * EH, nullptr,
                                                  e1, ns, acc, W_eb, W_ee, b_ee);
        else
            k_edge4<false, true><<<EGRID, 256>>>(edge_index, nullptr,
                                                 es0 + (size_t)t * E_C * EH, e1,
                                                 e1, ns, acc, W_eb, W_ee, b_ee);
        k_node4<<<NGRID, 256>>>(xin, hx, acc, W_nb,
                                xsB + (size_t)t * N_C * NH,
                                out_td + (size_t)t * N_C * NH);
        if (t < T_C - 1)
            k_global<<<1, 256>>>(W_gb, b_gb, W_eb, b_eb, W_nb, b_nb, 0);
        k_sder<<<E_C / 8, 256>>>(edge_index, spL, coeff,
                                 xsB + (size_t)t * N_C * NH,
                                 out_sd + (size_t)t * N_C * NH);
    }

    k_decode<<<(T_C * N_C) / 32, 256>>>(xsA, xsB, W_nd1, b_nd1, W_nd2, b_nd2, out);
}

// round 5
// speedup vs baseline: 1.1166x; 1.1166x over previous
#include <cuda_runtime.h>
#include <cstdint>

// Problem constants
#define T_C 4
#define N_C 20000
#define E_C 320000
#define FIN 12
#define EH 32
#define NH 64
#define GH 64

// ---------------- device scratch ----------------
__device__ float d_xenc[T_C * N_C * NH];
__device__ float d_xsA [T_C * N_C * NH];
__device__ float d_xsB [T_C * N_C * NH];
__device__ float d_es0 [(size_t)T_C * E_C * EH];
__device__ float d_e1  [(size_t)E_C * EH];
__device__ float d_hx0 [N_C * NH];
__device__ float d_ns  [N_C * NH];
__device__ float d_acc [N_C * NH];
__device__ float d_g[GH], d_gsave[GH];
__device__ float d_gce[EH];
__device__ float d_gcn[NH];
__device__ float d_esum[EH], d_xsum[NH];
__device__ float d_Pp[EH], d_Pm[EH];
__device__ int   d_fast0;

__device__ __forceinline__ float dot4(float4 v, float4 w) {
    return v.x * w.x + v.y * w.y + v.z * w.z + v.w * w.w;
}

// ---------------- small kernels ----------------

__global__ __launch_bounds__(256) void k_encode(const float* __restrict__ na,
                                                const float* __restrict__ W_ne,
                                                const float* __restrict__ b_ne,
                                                float* __restrict__ xenc) {
    __shared__ float sW[FIN * NH + NH];
    for (int i = threadIdx.x; i < FIN * NH + NH; i += 256)
        sW[i] = (i < FIN * NH) ? W_ne[i] : b_ne[i - FIN * NH];
    __syncthreads();
    int idx = blockIdx.x * 256 + threadIdx.x;
    int row = idx >> 6, j = idx & 63;
    float v = sW[FIN * NH + j];
#pragma unroll
    for (int k = 0; k < FIN; k++) v += na[row * FIN + k] * sW[k * NH + j];
    xenc[idx] = fmaxf(v, 0.f);
}

__global__ void k_prep(const float* __restrict__ W_ee, const float* __restrict__ b_ee,
                       const float* __restrict__ W_eb) {
    int j = threadIdx.x;  // 32
    float pp = 0.f, pm = 0.f;
    bool ok = true;
#pragma unroll
    for (int k = 0; k < EH; k++) {
        float w = W_ee[k];
        pp += fmaxf(w, 0.f)  * W_eb[k * EH + j];
        pm += fmaxf(-w, 0.f) * W_eb[k * EH + j];
        if (b_ee[k] != 0.f) ok = false;
    }
    d_Pp[j] = pp; d_Pm[j] = pm;
    if (j == 0) d_fast0 = ok ? 1 : 0;
}

__global__ void k_ginit(const float* __restrict__ g0,
                        const float* __restrict__ W_eb, const float* __restrict__ b_eb,
                        const float* __restrict__ W_nb, const float* __restrict__ b_nb) {
    __shared__ float g[GH];
    int tid = threadIdx.x;  // 96
    if (tid < GH) { g[tid] = g0[tid]; d_g[tid] = g0[tid]; }
    __syncthreads();
    if (tid < EH) {
        float v = b_eb[tid];
#pragma unroll
        for (int k = 0; k < GH; k++) v += g[k] * W_eb[(320 + k) * EH + tid];
        d_gce[tid] = v;
    } else if (tid < 32 + NH) {
        int j = tid - 32;
        float v = b_nb[j];
#pragma unroll
        for (int k = 0; k < GH; k++) v += g[k] * W_nb[(192 + k) * NH + j];
        d_gcn[j] = v;
    }
}

__global__ void k_global(const float* __restrict__ W_gb, const float* __restrict__ b_gb,
                         const float* __restrict__ W_eb, const float* __restrict__ b_eb,
                         const float* __restrict__ W_nb, const float* __restrict__ b_nb,
                         int save) {
    __shared__ float gcat[160], gnew[GH];
    int tid = threadIdx.x;  // 256
    if (tid < 64) gcat[tid] = d_xsum[tid] * (1.0f / N_C);
    else if (tid < 96) gcat[tid] = d_esum[tid - 64] * (1.0f / E_C);
    else if (tid < 160) gcat[tid] = d_g[tid - 96];
    __syncthreads();
    if (tid < GH) {
        float v = b_gb[tid];
        for (int k = 0; k < 160; k++) v += gcat[k] * W_gb[k * GH + tid];
        gnew[tid] = fmaxf(v, 0.f);
    }
    __syncthreads();
    if (tid < GH) {
        d_g[tid] = gnew[tid];
        if (save) d_gsave[tid] = gnew[tid];
        d_xsum[tid] = 0.f;
    }
    if (tid < EH) d_esum[tid] = 0.f;
    if (tid < EH) {
        float v = b_eb[tid];
#pragma unroll
        for (int k = 0; k < GH; k++) v += gnew[k] * W_eb[(320 + k) * EH + tid];
        d_gce[tid] = v;
    } else if (tid < 32 + NH) {
        int j = tid - 32;
        float v = b_nb[j];
#pragma unroll
        for (int k = 0; k < GH; k++) v += gnew[k] * W_nb[(192 + k) * NH + j];
        d_gcn[j] = v;
    }
}

// ---------------- k_nodepre5: 64 nodes/block, m4n4 SGEMM tile, K=128 ----------------
__global__ __launch_bounds__(256) void k_nodepre5(const float* __restrict__ xin,
                                                  const float* __restrict__ hx,
                                                  const float* __restrict__ W_eb,
                                                  float* __restrict__ ns,
                                                  float* __restrict__ accbuf) {
    extern __shared__ float sm[];
    float* sWt = sm;                 // [64][132]
    float* sv  = sm + 64 * 132;      // [64][132] (rows: [x|h], 128 used)
    int tid = threadIdx.x;
    int base = blockIdx.x * 64;
    for (int idx = tid; idx < 64 * 128; idx += 256) {
        int j = idx >> 7, k = idx & 127;
        sWt[j * 132 + k] = W_eb[((j < 32 ? 64 : 192) + k) * EH + (j & 31)];
    }
    const float4* x4 = (const float4*)xin;
    const float4* h4 = (const float4*)hx;
    for (int idx = tid; idx < 64 * 32; idx += 256) {
        int n = idx >> 5, q = idx & 31;
        int gn = base + n;
        float4 v = make_float4(0.f, 0.f, 0.f, 0.f);
        if (gn < N_C) v = (q < 16) ? x4[(size_t)gn * 16 + q] : h4[(size_t)gn * 16 + q - 16];
        *(float4*)&sv[n * 132 + 4 * q] = v;
    }
    __syncthreads();
    int og = tid & 15, ng = tid >> 4;
    float acc[16];
#pragma unroll
    for (int i = 0; i < 16; i++) acc[i] = 0.f;
#pragma unroll 8
    for (int kq = 0; kq < 32; kq++) {
        float4 v[4], w[4];
#pragma unroll
        for (int c = 0; c < 4; c++) v[c] = *(const float4*)&sv[(ng + 16 * c) * 132 + 4 * kq];
#pragma unroll
        for (int d = 0; d < 4; d++) w[d] = *(const float4*)&sWt[(og + 16 * d) * 132 + 4 * kq];
#pragma unroll
        for (int c = 0; c < 4; c++)
#pragma unroll
            for (int d = 0; d < 4; d++) acc[c * 4 + d] += dot4(v[c], w[d]);
    }
#pragma unroll
    for (int c = 0; c < 4; c++) {
        int gn = base + ng + 16 * c;
        if (gn < N_C) {
#pragma unroll
            for (int d = 0; d < 4; d++) {
                int j = og + 16 * d;
                ns[(size_t)gn * 64 + j] = acc[c * 4 + d];
                accbuf[(size_t)gn * 64 + j] = 0.f;
            }
        }
    }
}

// ---------------- k_edge5: 128 edges/block, m4n4 GEMV + lane=out tail ----------------
template <bool L0, bool HE>
__global__ __launch_bounds__(256) void k_edge5(const int* __restrict__ eidx,
                                               const float* __restrict__ ea_t,
                                               const float* __restrict__ ein,
                                               const float* __restrict__ he,
                                               float* __restrict__ eout,
                                               const float* __restrict__ ns,
                                               float* __restrict__ accbuf,
                                               const float* __restrict__ W_eb,
                                               const float* __restrict__ W_ee,
                                               const float* __restrict__ b_ee) {
    extern __shared__ float sm[];
    float* sWt  = sm;                      // [32][68]  (k 0..63 = ein|he rows)
    float* svA  = sm + 32 * 68;            // [128][36]
    float* svB  = svA + 128 * 36;          // [128][36]
    float* sacc = svB + 128 * 36;          // [128][33]
    int*   sidx = (int*)(sacc + 128 * 33); // [256]
    float* sa   = (float*)(sidx + 256);    // [128]
    float* sred = sa + 128;                // [256]
    int tid = threadIdx.x;
    int e0b = blockIdx.x * 128;
    int fast = L0 ? d_fast0 : 0;
    bool doEin = (!L0) || (!fast);

    for (int idx = tid; idx < 32 * 64; idx += 256) {
        int j = idx >> 6, k = idx & 63;
        sWt[j * 68 + k] = W_eb[k * EH + j];
    }
    if (tid < 128) {
        sidx[tid]       = eidx[e0b + tid];
        sidx[128 + tid] = eidx[E_C + e0b + tid];
        if (L0) sa[tid] = ea_t[e0b + tid];
    }
    if (L0) {
        if (!fast) {
            for (int idx = tid; idx < 128 * 32; idx += 256) {
                int e = idx >> 5, k = idx & 31;
                svA[e * 36 + k] = fmaxf(ea_t[e0b + e] * W_ee[k] + b_ee[k], 0.f);
            }
        }
    } else {
        const float4* p = (const float4*)(ein + (size_t)e0b * 32);
        for (int idx = tid; idx < 128 * 8; idx += 256) {
            int e = idx >> 3, q = idx & 7;
            *(float4*)&svA[e * 36 + 4 * q] = p[idx];
        }
    }
    if (HE) {
        const float4* p = (const float4*)(he + (size_t)e0b * 32);
        for (int idx = tid; idx < 128 * 8; idx += 256) {
            int e = idx >> 3, q = idx & 7;
            *(float4*)&svB[e * 36 + 4 * q] = p[idx];
        }
    }
    __syncthreads();

    int og = tid & 7, eg = tid >> 3;
    float acc[16];
#pragma unroll
    for (int i = 0; i < 16; i++) acc[i] = 0.f;
    if (doEin) {
#pragma unroll
        for (int kq = 0; kq < 8; kq++) {
            float4 v[4], w[4];
#pragma unroll
            for (int c = 0; c < 4; c++) v[c] = *(const float4*)&svA[(eg + 32 * c) * 36 + 4 * kq];
#pragma unroll
            for (int d = 0; d < 4; d++) w[d] = *(const float4*)&sWt[(og + 8 * d) * 68 + 4 * kq];
#pragma unroll
            for (int c = 0; c < 4; c++)
#pragma unroll
                for (int d = 0; d < 4; d++) acc[c * 4 + d] += dot4(v[c], w[d]);
        }
    }
    if (HE) {
#pragma unroll
        for (int kq = 0; kq < 8; kq++) {
            float4 v[4], w[4];
#pragma unroll
            for (int c = 0; c < 4; c++) v[c] = *(const float4*)&svB[(eg + 32 * c) * 36 + 4 * kq];
#pragma unroll
            for (int d = 0; d < 4; d++) w[d] = *(const float4*)&sWt[(og + 8 * d) * 68 + 32 + 4 * kq];
#pragma unroll
            for (int c = 0; c < 4; c++)
#pragma unroll
                for (int d = 0; d < 4; d++) acc[c * 4 + d] += dot4(v[c], w[d]);
        }
    }
#pragma unroll
    for (int c = 0; c < 4; c++)
#pragma unroll
        for (int d = 0; d < 4; d++)
            sacc[(eg + 32 * c) * 33 + og + 8 * d] = acc[c * 4 + d];
    __syncthreads();

    int lane = tid & 31, wid = tid >> 5;
    float gce = d_gce[lane];
    float pp = 0.f, pm = 0.f;
    if (L0 && fast) { pp = d_Pp[lane]; pm = d_Pm[lane]; }
    float esum = 0.f;
#pragma unroll 4
    for (int i = 0; i < 16; i++) {
        int el = wid * 16 + i;
        int s = sidx[el], r = sidx[128 + el];
        float a = sacc[el * 33 + lane] + gce;
        if (L0 && fast) {
            float av = sa[el];
            a += (av >= 0.f) ? av * pp : -av * pm;
        }
        float en = fmaxf(a + ns[(size_t)s * 64 + lane] + ns[(size_t)r * 64 + 32 + lane], 0.f);
        eout[(size_t)(e0b + el) * 32 + lane] = en;
        atomicAdd(&accbuf[(size_t)s * 64 + lane], en);
        atomicAdd(&accbuf[(size_t)r * 64 + 32 + lane], en);
        esum += en;
    }
    sred[wid * 32 + lane] = esum;
    __syncthreads();
    if (wid == 0) {
        float s2 = 0.f;
#pragma unroll
        for (int w = 0; w < 8; w++) s2 += sred[w * 32 + lane];
        atomicAdd(&d_esum[lane], s2);
    }
}

// ---------------- k_node5: 64 nodes/block, m4n4, K=192 ----------------
__global__ __launch_bounds__(256) void k_node5(const float* __restrict__ xin,
                                               const float* __restrict__ hx,
                                               const float* __restrict__ accb,
                                               const float* __restrict__ W_nb,
                                               float* __restrict__ xsout,
                                               float* __restrict__ tdout) {
    extern __shared__ float sm[];
    float* sWt  = sm;                    // [64][196]
    float* sv   = sm + 64 * 196;         // [64][196] (rows: [x|h|acc], 192 used)
    float* sred = sm + 2 * 64 * 196;     // [4][256]
    int tid = threadIdx.x;
    int base = blockIdx.x * 64;
    for (int idx = tid; idx < 64 * 192; idx += 256) {
        int j = idx / 192, k = idx - j * 192;
        sWt[j * 196 + k] = W_nb[k * NH + j];
    }
    const float4* x4 = (const float4*)xin;
    const float4* h4 = (const float4*)hx;
    const float4* a4 = (const float4*)accb;
    for (int idx = tid; idx < 64 * 48; idx += 256) {
        int n = idx / 48, q = idx - n * 48;
        int gn = base + n;
        float4 v = make_float4(0.f, 0.f, 0.f, 0.f);
        if (gn < N_C)
            v = (q < 16) ? x4[(size_t)gn * 16 + q]
              : (q < 32) ? h4[(size_t)gn * 16 + q - 16]
                         : a4[(size_t)gn * 16 + q - 32];
        *(float4*)&sv[n * 196 + 4 * q] = v;
    }
    __syncthreads();
    int og = tid & 15, ng = tid >> 4;
    float acc[16];
#pragma unroll
    for (int i = 0; i < 16; i++) acc[i] = 0.f;
#pragma unroll 8
    for (int kq = 0; kq < 48; kq++) {
        float4 v[4], w[4];
#pragma unroll
        for (int c = 0; c < 4; c++) v[c] = *(const float4*)&sv[(ng + 16 * c) * 196 + 4 * kq];
#pragma unroll
        for (int d = 0; d < 4; d++) w[d] = *(const float4*)&sWt[(og + 16 * d) * 196 + 4 * kq];
#pragma unroll
        for (int c = 0; c < 4; c++)
#pragma unroll
            for (int d = 0; d < 4; d++) acc[c * 4 + d] += dot4(v[c], w[d]);
    }
    float ps[4] = {0.f, 0.f, 0.f, 0.f};
#pragma unroll
    for (int c = 0; c < 4; c++) {
        int gn = base + ng + 16 * c;
        if (gn < N_C) {
#pragma unroll
            for (int d = 0; d < 4; d++) {
                int j = og + 16 * d;
                float v = fmaxf(acc[c * 4 + d] + d_gcn[j], 0.f);
                xsout[(size_t)gn * 64 + j] = v;
                if (tdout) tdout[(size_t)gn * 64 + j] = v - sv[(ng + 16 * c) * 196 + 64 + j];
                ps[d] += v;
            }
        }
    }
#pragma unroll
    for (int d = 0; d < 4; d++) sred[d * 256 + tid] = ps[d];
    __syncthreads();
    if (tid < 64) {
        int ogj = tid & 15, dj = tid >> 4;
        float s = 0.f;
#pragma unroll
        for (int g = 0; g < 16; g++) s += sred[dj * 256 + g * 16 + ogj];
        atomicAdd(&d_xsum[tid], s);
    }
}

// ---------------- sder / resid / decode ----------------
__global__ __launch_bounds__(256) void k_sder(const int* __restrict__ eidx,
                                              const float* __restrict__ spL,
                                              const float* __restrict__ coeff,
                                              const float* __restrict__ xs,
                                              float* __restrict__ sd) {
    int tid = threadIdx.x, lane = tid & 31, wid = tid >> 5;
    int e = blockIdx.x * 8 + wid;
    int s = eidx[e], r = eidx[E_C + e];
    float cw = coeff[0] * spL[e];
    size_t bs = (size_t)s * NH, br = (size_t)r * NH;
    float d0 = cw * (xs[bs + lane] - xs[br + lane]);
    float d1 = cw * (xs[bs + 32 + lane] - xs[br + 32 + lane]);
    atomicAdd(&sd[br + lane], d0);
    atomicAdd(&sd[br + 32 + lane], d1);
}

__global__ __launch_bounds__(256) void k_resid(float* __restrict__ a, const float* __restrict__ b) {
    int i = blockIdx.x * 256 + threadIdx.x;
    a[i] += b[i];
}

__global__ __launch_bounds__(256) void k_decode5(const float* __restrict__ xa,
                                                 const float* __restrict__ xb,
                                                 const float* __restrict__ W1,
                                                 const float* __restrict__ b1,
                                                 const float* __restrict__ W2,
                                                 const float* __restrict__ b2,
                                                 float* __restrict__ outn) {
    __shared__ float sWt[64 * 68];
    __shared__ float sv[64 * 68];
    int tid = threadIdx.x;
    int base = blockIdx.x * 64;   // 80000 / 64 = 1250
    for (int idx = tid; idx < 64 * 64; idx += 256) {
        int j = idx >> 6, k = idx & 63;
        sWt[j * 68 + k] = W1[k * NH + j];
    }
    const float4* a4 = (const float4*)xa;
    const float4* b4 = (const float4*)xb;
    for (int idx = tid; idx < 64 * 16; idx += 256) {
        int n = idx >> 4, q = idx & 15;
        float4 va = a4[(size_t)(base + n) * 16 + q];
        float4 vb = b4[(size_t)(base + n) * 16 + q];
        va.x += vb.x; va.y += vb.y; va.z += vb.z; va.w += vb.w;
        *(float4*)&sv[n * 68 + 4 * q] = va;
    }
    __syncthreads();
    int og = tid & 15, ng = tid >> 4;
    float acc[16];
#pragma unroll
    for (int i = 0; i < 16; i++) acc[i] = 0.f;
#pragma unroll
    for (int kq = 0; kq < 16; kq++) {
        float4 v[4], w[4];
#pragma unroll
        for (int c = 0; c < 4; c++) v[c] = *(const float4*)&sv[(ng + 16 * c) * 68 + 4 * kq];
#pragma unroll
        for (int d = 0; d < 4; d++) w[d] = *(const float4*)&sWt[(og + 16 * d) * 68 + 4 * kq];
#pragma unroll
        for (int c = 0; c < 4; c++)
#pragma unroll
            for (int d = 0; d < 4; d++) acc[c * 4 + d] += dot4(v[c], w[d]);
    }
    float w2[4], bb[4];
#pragma unroll
    for (int d = 0; d < 4; d++) { w2[d] = W2[og + 16 * d]; bb[d] = b1[og + 16 * d]; }
    float b20 = b2[0];
#pragma unroll
    for (int c = 0; c < 4; c++) {
        float p = 0.f;
#pragma unroll
        for (int d = 0; d < 4; d++) p += fmaxf(acc[c * 4 + d] + bb[d], 0.f) * w2[d];
        p += __shfl_down_sync(0xffffffffu, p, 8);
        p += __shfl_down_sync(0xffffffffu, p, 4);
        p += __shfl_down_sync(0xffffffffu, p, 2);
        p += __shfl_down_sync(0xffffffffu, p, 1);
        if (og == 0) outn[base + ng + 16 * c] = p + b20;
    }
}

// ---------------- host launcher ----------------
extern "C" void kernel_launch(void* const* d_in, const int* in_sizes, int n_in,
                              void* d_out, int out_size) {
    const float* node_attr  = (const float*)d_in[0];
    const float* edge_attr  = (const float*)d_in[1];
    const int*   edge_index = (const int*)  d_in[2];
    const float* spL        = (const float*)d_in[3];
    const float* gattr      = (const float*)d_in[4];
    const float* coeff      = (const float*)d_in[5];
    const float* W_ee = (const float*)d_in[6];
    const float* b_ee = (const float*)d_in[7];
    const float* W_ne = (const float*)d_in[8];
    const float* b_ne = (const float*)d_in[9];
    const float* W_eb = (const float*)d_in[10];
    const float* b_eb = (const float*)d_in[11];
    const float* W_nb = (const float*)d_in[12];
    const float* b_nb = (const float*)d_in[13];
    const float* W_gb = (const float*)d_in[14];
    const float* b_gb = (const float*)d_in[15];
    const float* W_nd1 = (const float*)d_in[16];
    const float* b_nd1 = (const float*)d_in[17];
    const float* W_nd2 = (const float*)d_in[18];
    const float* b_nd2 = (const float*)d_in[19];

    float* out    = (float*)d_out;
    float* out_td = out + (size_t)T_C * N_C;
    float* out_sd = out_td + (size_t)T_C * N_C * NH;

    float *xenc, *xsA, *xsB, *es0, *e1, *hx0, *ns, *acc, *gsave, *esum, *xsum;
    cudaGetSymbolAddress((void**)&xenc, d_xenc);
    cudaGetSymbolAddress((void**)&xsA,  d_xsA);
    cudaGetSymbolAddress((void**)&xsB,  d_xsB);
    cudaGetSymbolAddress((void**)&es0,  d_es0);
    cudaGetSymbolAddress((void**)&e1,   d_e1);
    cudaGetSymbolAddress((void**)&hx0,  d_hx0);
    cudaGetSymbolAddress((void**)&ns,   d_ns);
    cudaGetSymbolAddress((void**)&acc,  d_acc);
    cudaGetSymbolAddress((void**)&gsave, d_gsave);
    cudaGetSymbolAddress((void**)&esum, d_esum);
    cudaGetSymbolAddress((void**)&xsum, d_xsum);

    const int PRE_SMEM  = 2 * 64 * 132 * 4;                 // 67584
    const int NODE_SMEM = (2 * 64 * 196 + 4 * 256) * 4;     // 104448
    const int EDGE_SMEM = (32 * 68 + 2 * 128 * 36 + 128 * 33 + 256 + 128 + 256) * 4;  // 65024

    cudaFuncSetAttribute(k_nodepre5, cudaFuncAttributeMaxDynamicSharedMemorySize, PRE_SMEM);
    cudaFuncSetAttribute(k_node5,    cudaFuncAttributeMaxDynamicSharedMemorySize, NODE_SMEM);
    cudaFuncSetAttribute(k_edge5<true,  false>, cudaFuncAttributeMaxDynamicSharedMemorySize, EDGE_SMEM);
    cudaFuncSetAttribute(k_edge5<true,  true>,  cudaFuncAttributeMaxDynamicSharedMemorySize, EDGE_SMEM);
    cudaFuncSetAttribute(k_edge5<false, false>, cudaFuncAttributeMaxDynamicSharedMemorySize, EDGE_SMEM);
    cudaFuncSetAttribute(k_edge5<false, true>,  cudaFuncAttributeMaxDynamicSharedMemorySize, EDGE_SMEM);

    const int NGRID = (N_C + 63) / 64;   // 313
    const int EGRID = E_C / 128;         // 2500

    cudaMemsetAsync(hx0, 0, (size_t)N_C * NH * sizeof(float));
    cudaMemsetAsync(esum, 0, EH * sizeof(float));
    cudaMemsetAsync(xsum, 0, NH * sizeof(float));
    cudaMemsetAsync(out_sd, 0, (size_t)T_C * N_C * NH * sizeof(float));

    k_encode<<<(T_C * N_C * NH) / 256, 256>>>(node_attr, W_ne, b_ne, xenc);
    k_prep<<<1, 32>>>(W_ee, b_ee, W_eb);

    // ---------------- layer 0 ----------------
    k_ginit<<<1, 96>>>(gattr, W_eb, b_eb, W_nb, b_nb);
    for (int t = 0; t < T_C; t++) {
        const float* xin = xenc + (size_t)t * N_C * NH;
        const float* hx = t ? (xsA + (size_t)(t - 1) * N_C * NH) : hx0;
        k_nodepre5<<<NGRID, 256, PRE_SMEM>>>(xin, hx, W_eb, ns, acc);
        if (t == 0)
            k_edge5<true, false><<<EGRID, 256, EDGE_SMEM>>>(edge_index,
                edge_attr + (size_t)t * E_C, nullptr, nullptr,
                es0 + (size_t)t * E_C * EH, ns, acc, W_eb, W_ee, b_ee);
        else
            k_edge5<true, true><<<EGRID, 256, EDGE_SMEM>>>(edge_index,
                edge_attr + (size_t)t * E_C, nullptr, es0 + (size_t)(t - 1) * E_C * EH,
                es0 + (size_t)t * E_C * EH, ns, acc, W_eb, W_ee, b_ee);
        k_node5<<<NGRID, 256, NODE_SMEM>>>(xin, hx, acc, W_nb,
                                           xsA + (size_t)t * N_C * NH, nullptr);
        if (t < T_C - 1)
            k_global<<<1, 256>>>(W_gb, b_gb, W_eb, b_eb, W_nb, b_nb, t == 0 ? 1 : 0);
    }

    k_resid<<<(T_C * N_C * NH) / 256, 256>>>(xsA, xenc);
    cudaMemsetAsync(esum, 0, EH * sizeof(float));
    cudaMemsetAsync(xsum, 0, NH * sizeof(float));

    // ---------------- layer 1 ----------------
    k_ginit<<<1, 96>>>(gsave, W_eb, b_eb, W_nb, b_nb);
    for (int t = 0; t < T_C; t++) {
        const float* xin = xsA + (size_t)t * N_C * NH;
        const float* hx = t ? (xsB + (size_t)(t - 1) * N_C * NH) : hx0;
        k_nodepre5<<<NGRID, 256, PRE_SMEM>>>(xin, hx, W_eb, ns, acc);
        if (t == 0)
            k_edge5<false, false><<<EGRID, 256, EDGE_SMEM>>>(edge_index, nullptr,
                es0 + (size_t)t * E_C * EH, nullptr,
                e1, ns, acc, W_eb, W_ee, b_ee);
        else
            k_edge5<false, true><<<EGRID, 256, EDGE_SMEM>>>(edge_index, nullptr,
                es0 + (size_t)t * E_C * EH, e1,
                e1, ns, acc, W_eb, W_ee, b_ee);
        k_node5<<<NGRID, 256, NODE_SMEM>>>(xin, hx, acc, W_nb,
                                           xsB + (size_t)t * N_C * NH,
                                           out_td + (size_t)t * N_C * NH);
        if (t < T_C - 1)
            k_global<<<1, 256>>>(W_gb, b_gb, W_eb, b_eb, W_nb, b_nb, 0);
        k_sder<<<E_C / 8, 256>>>(edge_index, spL, coeff,
                                 xsB + (size_t)t * N_C * NH,
                                 out_sd + (size_t)t * N_C * NH);
    }

    k_decode5<<<(T_C * N_C) / 64, 256>>>(xsA, xsB, W_nd1, b_nd1, W_nd2, b_nd2, out);
}